// round 14
// baseline (speedup 1.0000x reference)
#include <cuda_runtime.h>

// Shapes fixed by the dataset
#define NN   8192
#define D    128
#define PP   256
#define KK   256
#define DEGN 32
#define FFN  16
#define TEMP_INV (1.0f/0.07f)
#define NB_NEG  (KK / 16)         // 16 negatives per block (2 per warp)
#define GRID    (PP + NB_NEG)

// Scratch (no allocations allowed)
__device__ __align__(16) float g_zq[D];          // normalized z[query]
__device__ __align__(16) float g_znx[DEGN * D];  // normalized z[N(q)]
__device__ float  g_te[DEGN];         // query-side time encodings
__device__ float  g_core_sum;
__device__ float  g_pos[PP];
__device__ float  g_align_arr[PP];
__device__ float  g_neg[KK];
__device__ unsigned int g_ctr;        // reset by k0 each launch

__device__ __forceinline__ float warpSum(float v) {
#pragma unroll
    for (int o = 16; o; o >>= 1) v += __shfl_xor_sync(0xffffffffu, v, o);
    return v;
}
__device__ __forceinline__ float octSum(float v) {   // 8-lane segments
#pragma unroll
    for (int o = 4; o; o >>= 1) v += __shfl_xor_sync(0xffffffffu, v, o);
    return v;
}
__device__ __forceinline__ float dot4(float4 a, float4 b) {
    return a.x*b.x + a.y*b.y + a.z*b.z + a.w*b.w;
}
__device__ __forceinline__ unsigned int ctrAddAcqRel(unsigned int* p) {
    unsigned int old;
    asm volatile("atom.add.acq_rel.gpu.global.u32 %0, [%1], 1;"
                 : "=r"(old) : "l"(p) : "memory");
    return old;
}

// ---------------------------------------------------------------------------
// k0: hoist p-invariant work (1 block x 1024 threads, warp-parallel)
// ---------------------------------------------------------------------------
__global__ void __launch_bounds__(1024) k0_setup(
        const float* __restrict__ z,
        const float* __restrict__ edge_times,
        const float* __restrict__ cur_t,
        const float* __restrict__ core,
        const float* __restrict__ omega,
        const float* __restrict__ phi,
        const int*   __restrict__ qidx,
        const int*   __restrict__ nbr_idxs,
        const int*   __restrict__ neighbors)
{
    __shared__ float red[32];
    const int tid = threadIdx.x;
    const int lane = tid & 31, warp = tid >> 5;
    const int q = qidx[0];
    const float ct = cur_t[0];

    if (tid == 0) g_ctr = 0;

    // warp 0: normalized z_q
    if (warp == 0) {
        float4 v = ((const float4*)(z + (size_t)q * D))[lane];
        float inv = rsqrtf(warpSum(dot4(v, v)));
        ((float4*)g_zq)[lane] = make_float4(v.x*inv, v.y*inv, v.z*inv, v.w*inv);
    }

    // warp w: normalized row N(q)[w] + te1[w]
    const int idx = neighbors[q * DEGN + warp];
    {
        float4 r = ((const float4*)(z + (size_t)idx * D))[lane];
        float inv = rsqrtf(warpSum(dot4(r, r)));
        ((float4*)g_znx)[warp * 32 + lane] =
            make_float4(r.x*inv, r.y*inv, r.z*inv, r.w*inv);
    }
    {
        float dt = 0.f;
        if (lane == 0) dt = ct - edge_times[(size_t)q * NN + idx];
        dt = __shfl_sync(0xffffffffu, dt, 0);
        float c = 0.f;
        if (lane == 0)       c = omega[0] * dt + phi[0];
        else if (lane < FFN) c = __sinf(omega[lane] * dt + phi[lane]);
        float te = warpSum(c);
        if (lane == 0) g_te[warp] = te;
    }

    // core proximity sum (threads 0..255)
    {
        float cd = 0.f;
        if (tid < PP) cd = core[nbr_idxs[tid]] - core[q];
        float cs = warpSum(cd * cd);
        if (lane == 0) red[warp] = cs;
        __syncthreads();
        if (tid == 0) {
            float t = 0.f;
            for (int i = 0; i < 8; i++) t += red[i];
            g_core_sum = t;
        }
    }
}

// ---------------------------------------------------------------------------
// k1: one block per p (8 warps x 4 j each) with in-block softmax.
//     Neg blocks: 2 negatives per warp. Last block: tiny scalar tail.
// ---------------------------------------------------------------------------
__global__ void __launch_bounds__(256)
k1_main(const float* __restrict__ z,
        const float* __restrict__ edge_times,
        const float* __restrict__ cur_t,
        const float* __restrict__ omega,
        const float* __restrict__ phi,
        const int*   __restrict__ neg_idxs,
        const int*   __restrict__ nbr_idxs,
        const int*   __restrict__ neighbors,
        float* __restrict__ out)
{
    __shared__ float s_acc[8][4];     // [warp][{W1,WM1,W2,WM2}]
    __shared__ float s_muxy;
    __shared__ float s_fr[3][8];
    __shared__ float s_f4[4];
    __shared__ unsigned int s_islast;

    const int tid  = threadIdx.x;
    const int lane = tid & 31, warp = tid >> 5;
    const int b    = blockIdx.x;
    const float ct = cur_t[0];

    if (b < PP) {
        const int p   = b;
        const int nbp = nbr_idxs[p];            // broadcast

        // 4 j's per warp: j_g = warp + 8*g
        const int j0 = warp, j1 = warp + 8, j2 = warp + 16, j3 = warp + 24;
        const int i0 = neighbors[nbp * DEGN + j0];
        const int i1 = neighbors[nbp * DEGN + j1];
        const int i2 = neighbors[nbp * DEGN + j2];
        const int i3 = neighbors[nbp * DEGN + j3];
        const float e0 = edge_times[(size_t)nbp * NN + i0];
        const float e1 = edge_times[(size_t)nbp * NN + i1];
        const float e2 = edge_times[(size_t)nbp * NN + i2];
        const float e3 = edge_times[(size_t)nbp * NN + i3];

        const float4 r0 = ((const float4*)(z + (size_t)i0 * D))[lane];
        const float4 r1 = ((const float4*)(z + (size_t)i1 * D))[lane];
        const float4 r2 = ((const float4*)(z + (size_t)i2 * D))[lane];
        const float4 r3 = ((const float4*)(z + (size_t)i3 * D))[lane];
        const float4 vb = ((const float4*)(z + (size_t)nbp * D))[lane]; // raw
        const float4 zq = ((const float4*)g_zq)[lane];                  // unit
        const float4 x0 = ((const float4*)g_znx)[j0 * 32 + lane];       // unit
        const float4 x1 = ((const float4*)g_znx)[j1 * 32 + lane];
        const float4 x2 = ((const float4*)g_znx)[j2 * 32 + lane];
        const float4 x3 = ((const float4*)g_znx)[j3 * 32 + lane];
        const float te10 = g_te[j0], te11 = g_te[j1];
        const float te12 = g_te[j2], te13 = g_te[j3];

        // 4 te2's in one pass: 8-lane segments, 2 sinusoid terms per lane
        const int g = lane >> 3, l = lane & 7;
        const float eg = (g == 0) ? e0 : (g == 1) ? e1 : (g == 2) ? e2 : e3;
        const float dt = ct - eg;
        const int fB = l + 8;
        float c = ((l == 0) ? (omega[0] * dt + phi[0])
                            : __sinf(omega[l] * dt + phi[l]))
                + __sinf(omega[fB] * dt + phi[fB]);

        // independent butterflies (ILP-overlapped)
        float ssb  = warpSum(dot4(vb, vb));
        float d10  = warpSum(dot4(x0, vb));
        float d11  = warpSum(dot4(x1, vb));
        float d12  = warpSum(dot4(x2, vb));
        float d13  = warpSum(dot4(x3, vb));
        float ssr0 = warpSum(dot4(r0, r0));
        float ssr1 = warpSum(dot4(r1, r1));
        float ssr2 = warpSum(dot4(r2, r2));
        float ssr3 = warpSum(dot4(r3, r3));
        float d20  = warpSum(dot4(r0, zq));
        float d21  = warpSum(dot4(r1, zq));
        float d22  = warpSum(dot4(r2, zq));
        float d23  = warpSum(dot4(r3, zq));
        float hc   = octSum(c);
        const float te20 = __shfl_sync(0xffffffffu, hc, 0);
        const float te21 = __shfl_sync(0xffffffffu, hc, 8);
        const float te22 = __shfl_sync(0xffffffffu, hc, 16);
        const float te23 = __shfl_sync(0xffffffffu, hc, 24);

        const float invb = rsqrtf(ssb);
        const float mu10 = 2.f * d10 * invb - 2.f;
        const float mu11 = 2.f * d11 * invb - 2.f;
        const float mu12 = 2.f * d12 * invb - 2.f;
        const float mu13 = 2.f * d13 * invb - 2.f;
        const float w10 = __expf(mu10 * TEMP_INV - te10);
        const float w11 = __expf(mu11 * TEMP_INV - te11);
        const float w12 = __expf(mu12 * TEMP_INV - te12);
        const float w13 = __expf(mu13 * TEMP_INV - te13);
        const float mu20 = 2.f * d20 * rsqrtf(ssr0) - 2.f;
        const float mu21 = 2.f * d21 * rsqrtf(ssr1) - 2.f;
        const float mu22 = 2.f * d22 * rsqrtf(ssr2) - 2.f;
        const float mu23 = 2.f * d23 * rsqrtf(ssr3) - 2.f;
        const float w20 = __expf(mu20 * TEMP_INV - te20);
        const float w21 = __expf(mu21 * TEMP_INV - te21);
        const float w22 = __expf(mu22 * TEMP_INV - te22);
        const float w23 = __expf(mu23 * TEMP_INV - te23);

        if (lane == 0) {
            s_acc[warp][0] = w10 + w11 + w12 + w13;
            s_acc[warp][1] = w10*mu10 + w11*mu11 + w12*mu12 + w13*mu13;
            s_acc[warp][2] = w20 + w21 + w22 + w23;
            s_acc[warp][3] = w20*mu20 + w21*mu21 + w22*mu22 + w23*mu23;
        }
        if (warp == 0) {
            float dqb = warpSum(dot4(vb, zq));
            if (lane == 0) s_muxy = 2.f * dqb * invb - 2.f;
        }
        __syncthreads();

        if (warp == 0) {
            // segmented reduce over 8 warps: lane reads s_acc[lane>>2][lane&3]
            float v = ((const float*)s_acc)[lane];
            v += __shfl_xor_sync(0xffffffffu, v, 16);
            v += __shfl_xor_sync(0xffffffffu, v, 8);
            v += __shfl_xor_sync(0xffffffffu, v, 4);
            if (lane < 4) s_f4[lane] = v;
            __syncwarp();
            if (lane == 0) {
                float term1 = s_f4[1] / (s_f4[0] + 1e-8f);
                float term2 = s_f4[3] / (s_f4[2] + 1e-8f);
                float d  = term1 + term2;        // lambda_T - lambda_S
                float ad = fabsf(d);
                g_align_arr[p] = (ad < 1.f) ? 0.5f * d * d : ad - 0.5f;
                float sgm = 1.f / (1.f + __expf(-s_muxy));
                g_pos[p] = -__logf(sgm + 1e-8f);
            }
        }
    } else {
        // ---------------- negative blocks (self-contained) ----------------
        const int ka  = (b - PP) * 16 + warp * 2;
        const int na  = neg_idxs[ka];
        const int nb2 = neg_idxs[ka + 1];
        const float4 va = ((const float4*)(z + (size_t)na  * D))[lane];
        const float4 vc = ((const float4*)(z + (size_t)nb2 * D))[lane];
        const float4 zq = ((const float4*)g_zq)[lane];   // unit (from k0)
        float ssa = warpSum(dot4(va, va));
        float ssc = warpSum(dot4(vc, vc));
        float da  = warpSum(dot4(va, zq));
        float dc  = warpSum(dot4(vc, zq));
        if (lane == 0) {
            float mua = 2.f * da * rsqrtf(ssa) - 2.f;
            float muc = 2.f * dc * rsqrtf(ssc) - 2.f;
            g_neg[ka]     = -__logf(1.f - 1.f / (1.f + __expf(-mua)) + 1e-8f);
            g_neg[ka + 1] = -__logf(1.f - 1.f / (1.f + __expf(-muc)) + 1e-8f);
        }
    }

    // ---- last-block gate: tiny scalar tail ----
    __syncthreads();
    if (tid == 0) {
        unsigned int t = ctrAddAcqRel(&g_ctr);
        s_islast = (t == (unsigned int)(GRID - 1));
    }
    __syncthreads();
    if (s_islast) {
        float a  = warpSum(__ldcg(&g_align_arr[tid]));
        float sp = warpSum(__ldcg(&g_pos[tid]));
        float sn = warpSum(__ldcg(&g_neg[tid]));
        if (lane == 0) {
            s_fr[0][warp] = a; s_fr[1][warp] = sp; s_fr[2][warp] = sn;
        }
        __syncthreads();
        if (tid == 0) {
            float A = 0.f, P = 0.f, Ng = 0.f;
#pragma unroll
            for (int i = 0; i < 8; i++) {
                A += s_fr[0][i]; P += s_fr[1][i]; Ng += s_fr[2][i];
            }
            out[0] = P / PP + Ng / KK
                   + 0.1f * (g_core_sum / PP)
                   + 0.1f * (A / PP);
            g_ctr = 0;    // reset for next graph replay
        }
    }
}

// ---------------------------------------------------------------------------
extern "C" void kernel_launch(void* const* d_in, const int* in_sizes, int n_in,
                              void* d_out, int out_size)
{
    const float* z          = (const float*)d_in[0];
    const float* edge_times = (const float*)d_in[1];
    const float* cur_t      = (const float*)d_in[2];
    const float* core       = (const float*)d_in[3];
    const float* omega      = (const float*)d_in[4];
    const float* phi        = (const float*)d_in[5];
    const int*   qidx       = (const int*)d_in[6];
    const int*   neg_idxs   = (const int*)d_in[7];
    const int*   nbr_idxs   = (const int*)d_in[8];
    const int*   neighbors  = (const int*)d_in[9];

    k0_setup<<<1, 1024>>>(z, edge_times, cur_t, core, omega, phi,
                          qidx, nbr_idxs, neighbors);
    k1_main<<<GRID, 256>>>(z, edge_times, cur_t, omega, phi,
                           neg_idxs, nbr_idxs, neighbors, (float*)d_out);
}

// round 15
// speedup vs baseline: 1.5581x; 1.5581x over previous
#include <cuda_runtime.h>

// Shapes fixed by the dataset
#define NN   8192
#define D    128
#define PP   256
#define KK   256
#define DEGN 32
#define FFN  16
#define TEMP_INV (1.0f/0.07f)
#define NB_TERM (PP * 2)          // 2 blocks per p, 8 warps, 2 j per warp
#define NB_NEG  (KK / 16)         // 16 negatives per block (2 per warp)
#define GRID    (NB_TERM + NB_NEG)

// Scratch (no allocations allowed)
__device__ float4 g_part[16 * PP];    // [jg][p] = {Sw1, Sw1mu1, Sw2, Sw2mu2}
__device__ float  g_pos[PP];
__device__ float  g_core[PP];
__device__ float  g_neg[KK];
__device__ unsigned int g_ctr;        // reset by last block each launch

__device__ __forceinline__ float warpSum(float v) {
#pragma unroll
    for (int o = 16; o; o >>= 1) v += __shfl_xor_sync(0xffffffffu, v, o);
    return v;
}
__device__ __forceinline__ float octSum(float v) {   // 8-lane segments
#pragma unroll
    for (int o = 4; o; o >>= 1) v += __shfl_xor_sync(0xffffffffu, v, o);
    return v;
}
__device__ __forceinline__ float dot4(float4 a, float4 b) {
    return a.x*b.x + a.y*b.y + a.z*b.z + a.w*b.w;
}
__device__ __forceinline__ unsigned int ctrAddAcqRel(unsigned int* p) {
    unsigned int old;
    asm volatile("atom.add.acq_rel.gpu.global.u32 %0, [%1], 1;"
                 : "=r"(old) : "l"(p) : "memory");
    return old;
}

// ---------------------------------------------------------------------------
// Single fused kernel, fully self-contained warps (no producer, no waiting).
// Term blocks (b < NB_TERM): p = b>>1, warp handles j = ja and ja+8.
// Neg blocks: 2 negatives per warp. Last block: tiny scalar tail.
// ---------------------------------------------------------------------------
__global__ void __launch_bounds__(256)
k_all(const float* __restrict__ z,
      const float* __restrict__ edge_times,
      const float* __restrict__ cur_t,
      const float* __restrict__ core,
      const float* __restrict__ omega,
      const float* __restrict__ phi,
      const int*   __restrict__ qidx,
      const int*   __restrict__ neg_idxs,
      const int*   __restrict__ nbr_idxs,
      const int*   __restrict__ neighbors,
      float* __restrict__ out)
{
    __shared__ float s_fr[3][8];
    __shared__ unsigned int s_islast;

    const int tid  = threadIdx.x;
    const int lane = tid & 31, warp = tid >> 5;
    const int b    = blockIdx.x;
    const int q    = qidx[0];            // broadcast
    const float ct = cur_t[0];

    if (b < NB_TERM) {
        const int p    = b >> 1;
        const int half = b & 1;
        const int ja   = half * 16 + warp;
        const int jb   = ja + 8;
        const int nbp  = nbr_idxs[p];

        // index gathers (broadcast within warp)
        const int nqa  = neighbors[q   * DEGN + ja];
        const int nqb  = neighbors[q   * DEGN + jb];
        const int ia   = neighbors[nbp * DEGN + ja];
        const int ib   = neighbors[nbp * DEGN + jb];
        const float etqa = edge_times[(size_t)q   * NN + nqa];
        const float etqb = edge_times[(size_t)q   * NN + nqb];
        const float eta  = edge_times[(size_t)nbp * NN + ia];
        const float etb  = edge_times[(size_t)nbp * NN + ib];

        // 6 row loads per warp (2 results)
        const float4 xa = ((const float4*)(z + (size_t)nqa * D))[lane];
        const float4 xb = ((const float4*)(z + (size_t)nqb * D))[lane];
        const float4 ra = ((const float4*)(z + (size_t)ia  * D))[lane];
        const float4 rb = ((const float4*)(z + (size_t)ib  * D))[lane];
        const float4 vb = ((const float4*)(z + (size_t)nbp * D))[lane];
        const float4 zq = ((const float4*)(z + (size_t)q   * D))[lane];

        // all 4 time encodings in one pass: 8-lane groups
        //   g0 -> (q, ja)   g1 -> (q, jb)   g2 -> (nbp, ja)   g3 -> (nbp, jb)
        const int g = lane >> 3, l = lane & 7;
        const float eg = (g == 0) ? etqa : (g == 1) ? etqb : (g == 2) ? eta : etb;
        const float dt = ct - eg;
        float c = ((l == 0) ? (omega[0] * dt + phi[0])
                            : __sinf(omega[l] * dt + phi[l]))
                + __sinf(omega[l + 8] * dt + phi[l + 8]);

        // independent butterflies (ILP-overlapped)
        float ssq  = warpSum(dot4(zq, zq));
        float ssb  = warpSum(dot4(vb, vb));
        float ssxa = warpSum(dot4(xa, xa));
        float ssxb = warpSum(dot4(xb, xb));
        float ssra = warpSum(dot4(ra, ra));
        float ssrb = warpSum(dot4(rb, rb));
        float d1a  = warpSum(dot4(xa, vb));
        float d1b  = warpSum(dot4(xb, vb));
        float d2a  = warpSum(dot4(ra, zq));
        float d2b  = warpSum(dot4(rb, zq));
        float hc   = octSum(c);
        const float te1a = __shfl_sync(0xffffffffu, hc, 0);
        const float te1b = __shfl_sync(0xffffffffu, hc, 8);
        const float te2a = __shfl_sync(0xffffffffu, hc, 16);
        const float te2b = __shfl_sync(0xffffffffu, hc, 24);

        const float invb = rsqrtf(ssb);
        const float invq = rsqrtf(ssq);
        const float mu1a = 2.f * d1a * rsqrtf(ssxa) * invb - 2.f;
        const float mu1b = 2.f * d1b * rsqrtf(ssxb) * invb - 2.f;
        const float w1a  = __expf(mu1a * TEMP_INV - te1a);
        const float w1b  = __expf(mu1b * TEMP_INV - te1b);
        const float mu2a = 2.f * d2a * rsqrtf(ssra) * invq - 2.f;
        const float mu2b = 2.f * d2b * rsqrtf(ssrb) * invq - 2.f;
        const float w2a  = __expf(mu2a * TEMP_INV - te2a);
        const float w2b  = __expf(mu2b * TEMP_INV - te2b);

        if (lane == 0)
            g_part[(half * 8 + warp) * PP + p] =
                make_float4(w1a + w1b,
                            w1a * mu1a + w1b * mu1b,
                            w2a + w2b,
                            w2a * mu2a + w2b * mu2b);

        if (half == 0 && warp == 0) {
            float dqb = warpSum(dot4(vb, zq));
            if (lane == 0) {
                float muxy = 2.f * dqb * invb * invq - 2.f;
                float sgm  = 1.f / (1.f + __expf(-muxy));
                g_pos[p] = -__logf(sgm + 1e-8f);
                float cd = core[nbp] - core[q];
                g_core[p] = cd * cd;
            }
        }
    } else {
        // ---------------- negative blocks (self-contained) ----------------
        const int ka  = (b - NB_TERM) * 16 + warp * 2;
        const int na  = neg_idxs[ka];
        const int nb2 = neg_idxs[ka + 1];
        const float4 va = ((const float4*)(z + (size_t)na  * D))[lane];
        const float4 vc = ((const float4*)(z + (size_t)nb2 * D))[lane];
        const float4 zq = ((const float4*)(z + (size_t)q   * D))[lane];
        float ssq = warpSum(dot4(zq, zq));
        float ssa = warpSum(dot4(va, va));
        float ssc = warpSum(dot4(vc, vc));
        float da  = warpSum(dot4(va, zq));
        float dc  = warpSum(dot4(vc, zq));
        if (lane == 0) {
            float invq = rsqrtf(ssq);
            float mua = 2.f * da * invq * rsqrtf(ssa) - 2.f;
            float muc = 2.f * dc * invq * rsqrtf(ssc) - 2.f;
            g_neg[ka]     = -__logf(1.f - 1.f / (1.f + __expf(-mua)) + 1e-8f);
            g_neg[ka + 1] = -__logf(1.f - 1.f / (1.f + __expf(-muc)) + 1e-8f);
        }
    }

    // ---- last-block gate ----
    __syncthreads();
    if (tid == 0) {
        unsigned int t = ctrAddAcqRel(&g_ctr);
        s_islast = (t == (unsigned int)(GRID - 1));
    }
    __syncthreads();
    if (s_islast) {
        // thread tid owns p = tid; jg-major -> coalesced float4 reads
        float W1 = 0.f, WM1 = 0.f, W2 = 0.f, WM2 = 0.f;
#pragma unroll
        for (int jg = 0; jg < 16; jg++) {
            float4 a = __ldcg(&g_part[jg * PP + tid]);
            W1 += a.x; WM1 += a.y; W2 += a.z; WM2 += a.w;
        }
        float term1 = WM1 / (W1 + 1e-8f);
        float term2 = WM2 / (W2 + 1e-8f);
        float d  = term1 + term2;            // lambda_T - lambda_S
        float ad = fabsf(d);
        float al = (ad < 1.f) ? 0.5f * d * d : ad - 0.5f;

        float a  = warpSum(al);
        float sp = warpSum(__ldcg(&g_pos[tid]));
        float sc = warpSum(__ldcg(&g_core[tid]));
        float sn = warpSum(__ldcg(&g_neg[tid]));
        if (lane == 0) {
            s_fr[0][warp] = a; s_fr[1][warp] = sp; s_fr[2][warp] = sn;
        }
        // core folded into s_fr via extra column trick: reuse s_fr[0..2] + shared
        __shared__ float s_core[8];
        if (lane == 0) s_core[warp] = sc;
        __syncthreads();
        if (tid == 0) {
            float A = 0.f, P = 0.f, Ng = 0.f, C = 0.f;
#pragma unroll
            for (int i = 0; i < 8; i++) {
                A += s_fr[0][i]; P += s_fr[1][i]; Ng += s_fr[2][i];
                C += s_core[i];
            }
            out[0] = P / PP + Ng / KK
                   + 0.1f * (C / PP)
                   + 0.1f * (A / PP);
            g_ctr = 0;    // reset for next graph replay
        }
    }
}

// ---------------------------------------------------------------------------
extern "C" void kernel_launch(void* const* d_in, const int* in_sizes, int n_in,
                              void* d_out, int out_size)
{
    const float* z          = (const float*)d_in[0];
    const float* edge_times = (const float*)d_in[1];
    const float* cur_t      = (const float*)d_in[2];
    const float* core       = (const float*)d_in[3];
    const float* omega      = (const float*)d_in[4];
    const float* phi        = (const float*)d_in[5];
    const int*   qidx       = (const int*)d_in[6];
    const int*   neg_idxs   = (const int*)d_in[7];
    const int*   nbr_idxs   = (const int*)d_in[8];
    const int*   neighbors  = (const int*)d_in[9];

    k_all<<<GRID, 256>>>(z, edge_times, cur_t, core, omega, phi,
                         qidx, neg_idxs, nbr_idxs, neighbors, (float*)d_out);
}

// round 16
// speedup vs baseline: 1.9634x; 1.2601x over previous
#include <cuda_runtime.h>

// Shapes fixed by the dataset
#define NN   8192
#define D    128
#define PP   256
#define KK   256
#define DEGN 32
#define FFN  16
#define TEMP_INV (1.0f/0.07f)
#define NB_NEG  (KK / 32)         // 8 blocks, 32 negatives each (2 per warp)
#define GRID    (PP + NB_NEG)     // 264 blocks x 512 threads

// Scratch (no allocations allowed)
__device__ float  g_pos[PP];
__device__ float  g_align_arr[PP];
__device__ float  g_core[PP];
__device__ float  g_neg[KK];
__device__ unsigned int g_ctr;        // reset by last block each launch

__device__ __forceinline__ float warpSum(float v) {
#pragma unroll
    for (int o = 16; o; o >>= 1) v += __shfl_xor_sync(0xffffffffu, v, o);
    return v;
}
__device__ __forceinline__ float dot4(float4 a, float4 b) {
    return a.x*b.x + a.y*b.y + a.z*b.z + a.w*b.w;
}
__device__ __forceinline__ unsigned int ctrAddAcqRel(unsigned int* p) {
    unsigned int old;
    asm volatile("atom.add.acq_rel.gpu.global.u32 %0, [%1], 1;"
                 : "=r"(old) : "l"(p) : "memory");
    return old;
}

// ---------------------------------------------------------------------------
// Single fused kernel, fully self-contained warps (no producer, no waiting).
// Term blocks (b < PP): one block per p; warp w (0..15) handles j = w, w+16.
// In-block softmax -> writes only {align, pos, core} scalars per p.
// Neg blocks: 2 negatives per warp. Last block: tiny scalar tail.
// ---------------------------------------------------------------------------
__global__ void __launch_bounds__(512)
k_all(const float* __restrict__ z,
      const float* __restrict__ edge_times,
      const float* __restrict__ cur_t,
      const float* __restrict__ core,
      const float* __restrict__ omega,
      const float* __restrict__ phi,
      const int*   __restrict__ qidx,
      const int*   __restrict__ neg_idxs,
      const int*   __restrict__ nbr_idxs,
      const int*   __restrict__ neighbors,
      float* __restrict__ out)
{
    __shared__ float s_acc[64];       // [warp][{W1,WM1,W2,WM2}] flat
    __shared__ float s_muxy;
    __shared__ float s_fr[4][16];
    __shared__ unsigned int s_islast;

    const int tid  = threadIdx.x;
    const int lane = tid & 31, warp = tid >> 5;
    const int b    = blockIdx.x;
    const int q    = qidx[0];            // broadcast
    const float ct = cur_t[0];

    if (b < PP) {
        const int p   = b;
        const int ja  = warp;            // 0..15
        const int jb  = warp + 16;       // 16..31
        const int nbp = nbr_idxs[p];

        // index gathers (broadcast within warp)
        const int nqa  = neighbors[q   * DEGN + ja];
        const int nqb  = neighbors[q   * DEGN + jb];
        const int ia   = neighbors[nbp * DEGN + ja];
        const int ib   = neighbors[nbp * DEGN + jb];
        const float etqa = edge_times[(size_t)q   * NN + nqa];
        const float etqb = edge_times[(size_t)q   * NN + nqb];
        const float eta  = edge_times[(size_t)nbp * NN + ia];
        const float etb  = edge_times[(size_t)nbp * NN + ib];

        // 6 row loads per warp (2 results)
        const float4 xa = ((const float4*)(z + (size_t)nqa * D))[lane];
        const float4 xb = ((const float4*)(z + (size_t)nqb * D))[lane];
        const float4 ra = ((const float4*)(z + (size_t)ia  * D))[lane];
        const float4 rb = ((const float4*)(z + (size_t)ib  * D))[lane];
        const float4 vb = ((const float4*)(z + (size_t)nbp * D))[lane];
        const float4 zq = ((const float4*)(z + (size_t)q   * D))[lane];

        // all 4 time encodings in one pass: 8-lane groups
        //   g0 -> (q, ja)   g1 -> (q, jb)   g2 -> (nbp, ja)   g3 -> (nbp, jb)
        const int g = lane >> 3, l = lane & 7;
        const float eg = (g == 0) ? etqa : (g == 1) ? etqb : (g == 2) ? eta : etb;
        const float dt = ct - eg;
        float c = ((l == 0) ? (omega[0] * dt + phi[0])
                            : __sinf(omega[l] * dt + phi[l]))
                + __sinf(omega[l + 8] * dt + phi[l + 8]);

        // independent butterflies (ILP-overlapped)
        float ssq  = warpSum(dot4(zq, zq));
        float ssb  = warpSum(dot4(vb, vb));
        float ssxa = warpSum(dot4(xa, xa));
        float ssxb = warpSum(dot4(xb, xb));
        float ssra = warpSum(dot4(ra, ra));
        float ssrb = warpSum(dot4(rb, rb));
        float d1a  = warpSum(dot4(xa, vb));
        float d1b  = warpSum(dot4(xb, vb));
        float d2a  = warpSum(dot4(ra, zq));
        float d2b  = warpSum(dot4(rb, zq));
        float hc = c;
#pragma unroll
        for (int o = 4; o; o >>= 1) hc += __shfl_xor_sync(0xffffffffu, hc, o);
        const float te1a = __shfl_sync(0xffffffffu, hc, 0);
        const float te1b = __shfl_sync(0xffffffffu, hc, 8);
        const float te2a = __shfl_sync(0xffffffffu, hc, 16);
        const float te2b = __shfl_sync(0xffffffffu, hc, 24);

        const float invb = rsqrtf(ssb);
        const float invq = rsqrtf(ssq);
        const float mu1a = 2.f * d1a * rsqrtf(ssxa) * invb - 2.f;
        const float mu1b = 2.f * d1b * rsqrtf(ssxb) * invb - 2.f;
        const float w1a  = __expf(mu1a * TEMP_INV - te1a);
        const float w1b  = __expf(mu1b * TEMP_INV - te1b);
        const float mu2a = 2.f * d2a * rsqrtf(ssra) * invq - 2.f;
        const float mu2b = 2.f * d2b * rsqrtf(ssrb) * invq - 2.f;
        const float w2a  = __expf(mu2a * TEMP_INV - te2a);
        const float w2b  = __expf(mu2b * TEMP_INV - te2b);

        if (lane == 0) {
            s_acc[warp * 4 + 0] = w1a + w1b;
            s_acc[warp * 4 + 1] = w1a * mu1a + w1b * mu1b;
            s_acc[warp * 4 + 2] = w2a + w2b;
            s_acc[warp * 4 + 3] = w2a * mu2a + w2b * mu2b;
        }
        if (warp == 0) {
            float dqb = warpSum(dot4(vb, zq));
            if (lane == 0) s_muxy = 2.f * dqb * invb * invq - 2.f;
        }
        __syncthreads();

        if (warp == 0) {
            // 64 floats -> 4 sums: lane reads flat[lane] + flat[lane+32]
            // (same k = idx&3, warps w and w+8), then stride-4 butterfly.
            float v = s_acc[lane] + s_acc[lane + 32];
            v += __shfl_xor_sync(0xffffffffu, v, 16);
            v += __shfl_xor_sync(0xffffffffu, v, 8);
            v += __shfl_xor_sync(0xffffffffu, v, 4);
            // lanes 0..3 hold {W1, WM1, W2, WM2}
            float W1  = __shfl_sync(0xffffffffu, v, 0);
            float WM1 = __shfl_sync(0xffffffffu, v, 1);
            float W2  = __shfl_sync(0xffffffffu, v, 2);
            float WM2 = __shfl_sync(0xffffffffu, v, 3);
            if (lane == 0) {
                float term1 = WM1 / (W1 + 1e-8f);
                float term2 = WM2 / (W2 + 1e-8f);
                float d  = term1 + term2;        // lambda_T - lambda_S
                float ad = fabsf(d);
                g_align_arr[p] = (ad < 1.f) ? 0.5f * d * d : ad - 0.5f;
                float sgm = 1.f / (1.f + __expf(-s_muxy));
                g_pos[p] = -__logf(sgm + 1e-8f);
                float cd = core[nbp] - core[q];
                g_core[p] = cd * cd;
            }
        }
    } else {
        // ---------------- negative blocks (self-contained) ----------------
        const int ka  = (b - PP) * 32 + warp * 2;
        const int na  = neg_idxs[ka];
        const int nb2 = neg_idxs[ka + 1];
        const float4 va = ((const float4*)(z + (size_t)na  * D))[lane];
        const float4 vc = ((const float4*)(z + (size_t)nb2 * D))[lane];
        const float4 zq = ((const float4*)(z + (size_t)q   * D))[lane];
        float ssq = warpSum(dot4(zq, zq));
        float ssa = warpSum(dot4(va, va));
        float ssc = warpSum(dot4(vc, vc));
        float da  = warpSum(dot4(va, zq));
        float dc  = warpSum(dot4(vc, zq));
        if (lane == 0) {
            float invq = rsqrtf(ssq);
            float mua = 2.f * da * invq * rsqrtf(ssa) - 2.f;
            float muc = 2.f * dc * invq * rsqrtf(ssc) - 2.f;
            g_neg[ka]     = -__logf(1.f - 1.f / (1.f + __expf(-mua)) + 1e-8f);
            g_neg[ka + 1] = -__logf(1.f - 1.f / (1.f + __expf(-muc)) + 1e-8f);
        }
    }

    // ---- last-block gate: one latency round of 1KB coalesced reads ----
    __syncthreads();
    if (tid == 0) {
        unsigned int t = ctrAddAcqRel(&g_ctr);
        s_islast = (t == (unsigned int)(GRID - 1));
    }
    __syncthreads();
    if (s_islast) {
        float al = 0.f, sp = 0.f, sc = 0.f, sn = 0.f;
        if (tid < PP) {
            al = __ldcg(&g_align_arr[tid]);
            sp = __ldcg(&g_pos[tid]);
            sc = __ldcg(&g_core[tid]);
            sn = __ldcg(&g_neg[tid]);
        }
        al = warpSum(al); sp = warpSum(sp);
        sc = warpSum(sc); sn = warpSum(sn);
        if (lane == 0) {
            s_fr[0][warp] = al; s_fr[1][warp] = sp;
            s_fr[2][warp] = sc; s_fr[3][warp] = sn;
        }
        __syncthreads();
        if (tid == 0) {
            float A = 0.f, P = 0.f, C = 0.f, Ng = 0.f;
#pragma unroll
            for (int i = 0; i < 16; i++) {
                A += s_fr[0][i]; P += s_fr[1][i];
                C += s_fr[2][i]; Ng += s_fr[3][i];
            }
            out[0] = P / PP + Ng / KK
                   + 0.1f * (C / PP)
                   + 0.1f * (A / PP);
            g_ctr = 0;    // reset for next graph replay
        }
    }
}

// ---------------------------------------------------------------------------
extern "C" void kernel_launch(void* const* d_in, const int* in_sizes, int n_in,
                              void* d_out, int out_size)
{
    const float* z          = (const float*)d_in[0];
    const float* edge_times = (const float*)d_in[1];
    const float* cur_t      = (const float*)d_in[2];
    const float* core       = (const float*)d_in[3];
    const float* omega      = (const float*)d_in[4];
    const float* phi        = (const float*)d_in[5];
    const int*   qidx       = (const int*)d_in[6];
    const int*   neg_idxs   = (const int*)d_in[7];
    const int*   nbr_idxs   = (const int*)d_in[8];
    const int*   neighbors  = (const int*)d_in[9];

    k_all<<<GRID, 512>>>(z, edge_times, cur_t, core, omega, phi,
                         qidx, neg_idxs, nbr_idxs, neighbors, (float*)d_out);
}